// round 15
// baseline (speedup 1.0000x reference)
#include <cuda_runtime.h>
#include <math_constants.h>

// Problem constants (fixed shapes from reference setup_inputs)
#define B 128
#define C 128
#define HW 4096          // 64*64
#define NPLANES (B*C)    // 16384
#define LIFETIME_K 6

// Persistent grid: 8 blocks/SM x 148 SMs (24 regs, 256 thr -> 8 resident)
#define PERSIST_BLOCKS 1184

// Scratch (no cudaMalloc allowed) — both transposed [C, B] for coalesced tail loads
__device__ float g_pooledT[NPLANES];
__device__ int   g_pidxT[NPLANES];

// ---------------------------------------------------------------------------
// Kernel 1 (fused, persistent): each of 1184 resident blocks grid-strides over
// ~14 planes. Per plane: 4 float4 zero-stores (independent, issued first) +
// 4 float4 loads + max/first-argmax reduction -> pooledT/pidxT (transposed).
// Persistence removes ~13 wave transitions vs the 16384-block launch.
// ---------------------------------------------------------------------------
__global__ __launch_bounds__(256) void pool_zero_kernel(const float* __restrict__ in,
                                                        float4* __restrict__ out4,
                                                        float* __restrict__ pooledT,
                                                        int* __restrict__ pidxT) {
    const int t = threadIdx.x;
    const int warp = t >> 5;
    const int lane = t & 31;

    __shared__ float sv[8];
    __shared__ int   si[8];

    for (int plane = blockIdx.x; plane < NPLANES; plane += PERSIST_BLOCKS) {
        // ---- independent zero stores for this plane's output (16 KB) ----
        {
            const float4 z = make_float4(0.f, 0.f, 0.f, 0.f);
            float4* o = out4 + (size_t)plane * (HW / 4) + t;
            #pragma unroll
            for (int k = 0; k < 4; k++)
                __stcs(o + k * 256, z);
        }

        // ---- input reduction: max + first-argmax ----
        const float4* p = reinterpret_cast<const float4*>(in + (size_t)plane * HW);

        float best = -CUDART_INF_F;
        int   bi   = 0x7fffffff;

        #pragma unroll
        for (int k = 0; k < 4; k++) {
            const int v4 = t + k * 256;          // float4 index, coalesced across warp
            const float4 v = __ldcs(p + v4);
            const int base = v4 * 4;
            // within-thread indices are strictly increasing -> strict > keeps first max
            if (v.x > best) { best = v.x; bi = base + 0; }
            if (v.y > best) { best = v.y; bi = base + 1; }
            if (v.z > best) { best = v.z; bi = base + 2; }
            if (v.w > best) { best = v.w; bi = base + 3; }
        }

        // warp reduce (value desc, index asc on ties -> first-max semantics)
        #pragma unroll
        for (int o = 16; o; o >>= 1) {
            const float ov = __shfl_down_sync(0xffffffffu, best, o);
            const int   oi = __shfl_down_sync(0xffffffffu, bi,   o);
            if (ov > best || (ov == best && oi < bi)) { best = ov; bi = oi; }
        }

        if (lane == 0) { sv[warp] = best; si[warp] = bi; }
        __syncthreads();

        if (warp == 0) {
            best = (lane < 8) ? sv[lane] : -CUDART_INF_F;
            bi   = (lane < 8) ? si[lane] : 0x7fffffff;
            #pragma unroll
            for (int o = 4; o; o >>= 1) {
                const float ov = __shfl_down_sync(0xffffffffu, best, o);
                const int   oi = __shfl_down_sync(0xffffffffu, bi,   o);
                if (ov > best || (ov == best && oi < bi)) { best = ov; bi = oi; }
            }
            if (lane == 0) {
                const int c = plane & (C - 1);
                const int b = plane >> 7;        // plane / C
                pooledT[c * B + b] = best;       // transposed stores
                pidxT[c * B + b] = bi;
            }
        }
        __syncthreads();   // protect sv/si reuse across loop iterations
    }
}

// ---------------------------------------------------------------------------
// Kernel 2 (tail): one warp per feature, 128 blocks x 32 threads.
// All 8 loads (4 pooled values + 4 argmax indices, coalesced from transposed
// arrays) issued up front at MLP=8. Top-6 over batch (value desc, batch asc
// on ties = jax.lax.top_k stability), then point-scatter. PDL launch.
// ---------------------------------------------------------------------------
__global__ __launch_bounds__(32) void topk_scatter_kernel(const float* __restrict__ pooledT,
                                                          const int* __restrict__ pidxT,
                                                          float* __restrict__ out) {
    cudaGridDependencySynchronize();

    const int lane = threadIdx.x;
    const int c = blockIdx.x;

    // lane owns batches b = lane, lane+32, lane+64, lane+96 (in-thread b ascending)
    float v[4];
    int   ip[4];
    #pragma unroll
    for (int k = 0; k < 4; k++) {
        v[k]  = pooledT[c * B + lane + k * 32];
        ip[k] = pidxT [c * B + lane + k * 32];
    }

    float cur[4] = {v[0], v[1], v[2], v[3]};
    unsigned selmask = 0;

    #pragma unroll
    for (int r = 0; r < LIFETIME_K; r++) {
        // local argmax: k ascending means b ascending, strict > keeps smallest b
        float lv = cur[0]; int lk = 0;
        #pragma unroll
        for (int k = 1; k < 4; k++)
            if (cur[k] > lv) { lv = cur[k]; lk = k; }
        float bv = lv;
        int   bb = lane + lk * 32;           // global batch index

        // butterfly reduce: max value, tie -> smaller batch index
        #pragma unroll
        for (int o = 16; o; o >>= 1) {
            const float ov = __shfl_xor_sync(0xffffffffu, bv, o);
            const int   ob = __shfl_xor_sync(0xffffffffu, bb, o);
            if (ov > bv || (ov == bv && ob < bb)) { bv = ov; bb = ob; }
        }
        // winner lane retires its value
        if ((bb & 31) == lane) {
            const int k = bb >> 5;
            cur[k] = -CUDART_INF_F;
            selmask |= 1u << k;
        }
    }

    // scatter: each lane writes its 4 planes' single elements
    #pragma unroll
    for (int k = 0; k < 4; k++) {
        const int b = lane + k * 32;
        const int plane = b * C + c;
        const float life = ((selmask >> k) & 1u) ? v[k] : 0.0f;
        out[(size_t)plane * HW + ip[k]] = life;
    }
}

// ---------------------------------------------------------------------------
extern "C" void kernel_launch(void* const* d_in, const int* in_sizes, int n_in,
                              void* d_out, int out_size) {
    const float* act = (const float*)d_in[0];
    float* out = (float*)d_out;

    float* pooledT; cudaGetSymbolAddress((void**)&pooledT, g_pooledT);
    int*   pidxT;   cudaGetSymbolAddress((void**)&pidxT,   g_pidxT);

    pool_zero_kernel<<<PERSIST_BLOCKS, 256>>>(act, (float4*)out, pooledT, pidxT);

    // PDL launch of the dependent epilogue kernel
    cudaLaunchConfig_t cfg = {};
    cfg.gridDim = dim3(C);
    cfg.blockDim = dim3(32);
    cfg.dynamicSmemBytes = 0;
    cfg.stream = 0;  // same (captured) default stream
    cudaLaunchAttribute attrs[1];
    attrs[0].id = cudaLaunchAttributeProgrammaticStreamSerialization;
    attrs[0].val.programmaticStreamSerializationAllowed = 1;
    cfg.attrs = attrs;
    cfg.numAttrs = 1;
    cudaLaunchKernelEx(&cfg, topk_scatter_kernel,
                       (const float*)pooledT, (const int*)pidxT, out);
}

// round 17
// speedup vs baseline: 1.0948x; 1.0948x over previous
#include <cuda_runtime.h>
#include <math_constants.h>

// Problem constants (fixed shapes from reference setup_inputs)
#define B 128
#define C 128
#define HW 4096          // 64*64
#define NPLANES (B*C)    // 16384
#define LIFETIME_K 6

// Scratch (no cudaMalloc allowed) — both transposed [C, B] for coalesced tail loads
__device__ float g_pooledT[NPLANES];
__device__ int   g_pidxT[NPLANES];

// ---------------------------------------------------------------------------
// Kernel 1 (fused): TWO planes per block (grid 8192, straight-line).
// Per block: 8 independent float4 zero-stores (both planes) issued first,
// then plane A loads+warp-reduce, plane B loads+warp-reduce (B's loads are
// independent of A's reduction -> deep MLP), ONE barrier, then warp0/warp1
// do the final cross-warp reductions for A/B in parallel.
// pooled/pidx written TRANSPOSED so the tail kernel loads coalesced.
// ---------------------------------------------------------------------------
__global__ __launch_bounds__(256) void pool_zero_kernel(const float* __restrict__ in,
                                                        float4* __restrict__ out4,
                                                        float* __restrict__ pooledT,
                                                        int* __restrict__ pidxT) {
    const int p0 = blockIdx.x * 2;           // planes p0, p0+1
    const int t = threadIdx.x;
    const int warp = t >> 5;
    const int lane = t & 31;

    // ---- independent zero stores for both output planes (32 KB contiguous) ----
    {
        const float4 z = make_float4(0.f, 0.f, 0.f, 0.f);
        float4* o = out4 + (size_t)p0 * (HW / 4) + t;
        #pragma unroll
        for (int k = 0; k < 8; k++)
            __stcs(o + k * 256, z);
    }

    const float4* pa = reinterpret_cast<const float4*>(in + (size_t)p0 * HW);

    // ---- plane A: loads + in-thread + warp reduce ----
    float bestA = -CUDART_INF_F; int biA = 0x7fffffff;
    #pragma unroll
    for (int k = 0; k < 4; k++) {
        const int v4 = t + k * 256;
        const float4 v = __ldcs(pa + v4);
        const int base = v4 * 4;
        if (v.x > bestA) { bestA = v.x; biA = base + 0; }
        if (v.y > bestA) { bestA = v.y; biA = base + 1; }
        if (v.z > bestA) { bestA = v.z; biA = base + 2; }
        if (v.w > bestA) { bestA = v.w; biA = base + 3; }
    }

    // ---- plane B: loads + in-thread + warp reduce (independent of A) ----
    float bestB = -CUDART_INF_F; int biB = 0x7fffffff;
    #pragma unroll
    for (int k = 0; k < 4; k++) {
        const int v4 = t + k * 256;
        const float4 v = __ldcs(pa + 1024 + v4);     // plane p0+1
        const int base = v4 * 4;
        if (v.x > bestB) { bestB = v.x; biB = base + 0; }
        if (v.y > bestB) { bestB = v.y; biB = base + 1; }
        if (v.z > bestB) { bestB = v.z; biB = base + 2; }
        if (v.w > bestB) { bestB = v.w; biB = base + 3; }
    }

    // warp reduces (value desc, index asc on ties -> first-max semantics)
    #pragma unroll
    for (int o = 16; o; o >>= 1) {
        const float ovA = __shfl_down_sync(0xffffffffu, bestA, o);
        const int   oiA = __shfl_down_sync(0xffffffffu, biA,   o);
        if (ovA > bestA || (ovA == bestA && oiA < biA)) { bestA = ovA; biA = oiA; }
        const float ovB = __shfl_down_sync(0xffffffffu, bestB, o);
        const int   oiB = __shfl_down_sync(0xffffffffu, biB,   o);
        if (ovB > bestB || (ovB == bestB && oiB < biB)) { bestB = ovB; biB = oiB; }
    }

    __shared__ float sv[2][8];
    __shared__ int   si[2][8];
    if (lane == 0) {
        sv[0][warp] = bestA; si[0][warp] = biA;
        sv[1][warp] = bestB; si[1][warp] = biB;
    }
    __syncthreads();

    // warp0 finalizes plane A, warp1 finalizes plane B (parallel)
    if (warp < 2) {
        float best = (lane < 8) ? sv[warp][lane] : -CUDART_INF_F;
        int   bi   = (lane < 8) ? si[warp][lane] : 0x7fffffff;
        #pragma unroll
        for (int o = 4; o; o >>= 1) {
            const float ov = __shfl_down_sync(0xffffffffu, best, o);
            const int   oi = __shfl_down_sync(0xffffffffu, bi,   o);
            if (ov > best || (ov == best && oi < bi)) { best = ov; bi = oi; }
        }
        if (lane == 0) {
            const int plane = p0 + warp;
            const int c = plane & (C - 1);
            const int b = plane >> 7;            // plane / C
            pooledT[c * B + b] = best;           // transposed stores
            pidxT[c * B + b] = bi;
        }
    }
}

// ---------------------------------------------------------------------------
// Kernel 2 (tail): one warp per feature, 128 blocks x 32 threads.
// All 8 loads (4 pooled values + 4 argmax indices, coalesced from transposed
// arrays) issued up front at MLP=8. Top-6 over batch (value desc, batch asc
// on ties = jax.lax.top_k stability), then point-scatter. PDL launch.
// ---------------------------------------------------------------------------
__global__ __launch_bounds__(32) void topk_scatter_kernel(const float* __restrict__ pooledT,
                                                          const int* __restrict__ pidxT,
                                                          float* __restrict__ out) {
    cudaGridDependencySynchronize();

    const int lane = threadIdx.x;
    const int c = blockIdx.x;

    // lane owns batches b = lane, lane+32, lane+64, lane+96 (in-thread b ascending)
    float v[4];
    int   ip[4];
    #pragma unroll
    for (int k = 0; k < 4; k++) {
        v[k]  = pooledT[c * B + lane + k * 32];
        ip[k] = pidxT [c * B + lane + k * 32];
    }

    float cur[4] = {v[0], v[1], v[2], v[3]};
    unsigned selmask = 0;

    #pragma unroll
    for (int r = 0; r < LIFETIME_K; r++) {
        // local argmax: k ascending means b ascending, strict > keeps smallest b
        float lv = cur[0]; int lk = 0;
        #pragma unroll
        for (int k = 1; k < 4; k++)
            if (cur[k] > lv) { lv = cur[k]; lk = k; }
        float bv = lv;
        int   bb = lane + lk * 32;           // global batch index

        // butterfly reduce: max value, tie -> smaller batch index
        #pragma unroll
        for (int o = 16; o; o >>= 1) {
            const float ov = __shfl_xor_sync(0xffffffffu, bv, o);
            const int   ob = __shfl_xor_sync(0xffffffffu, bb, o);
            if (ov > bv || (ov == bv && ob < bb)) { bv = ov; bb = ob; }
        }
        // winner lane retires its value
        if ((bb & 31) == lane) {
            const int k = bb >> 5;
            cur[k] = -CUDART_INF_F;
            selmask |= 1u << k;
        }
    }

    // scatter: each lane writes its 4 planes' single elements
    #pragma unroll
    for (int k = 0; k < 4; k++) {
        const int b = lane + k * 32;
        const int plane = b * C + c;
        const float life = ((selmask >> k) & 1u) ? v[k] : 0.0f;
        out[(size_t)plane * HW + ip[k]] = life;
    }
}

// ---------------------------------------------------------------------------
extern "C" void kernel_launch(void* const* d_in, const int* in_sizes, int n_in,
                              void* d_out, int out_size) {
    const float* act = (const float*)d_in[0];
    float* out = (float*)d_out;

    float* pooledT; cudaGetSymbolAddress((void**)&pooledT, g_pooledT);
    int*   pidxT;   cudaGetSymbolAddress((void**)&pidxT,   g_pidxT);

    pool_zero_kernel<<<NPLANES / 2, 256>>>(act, (float4*)out, pooledT, pidxT);

    // PDL launch of the dependent epilogue kernel
    cudaLaunchConfig_t cfg = {};
    cfg.gridDim = dim3(C);
    cfg.blockDim = dim3(32);
    cfg.dynamicSmemBytes = 0;
    cfg.stream = 0;  // same (captured) default stream
    cudaLaunchAttribute attrs[1];
    attrs[0].id = cudaLaunchAttributeProgrammaticStreamSerialization;
    attrs[0].val.programmaticStreamSerializationAllowed = 1;
    cfg.attrs = attrs;
    cfg.numAttrs = 1;
    cudaLaunchKernelEx(&cfg, topk_scatter_kernel,
                       (const float*)pooledT, (const int*)pidxT, out);
}